// round 11
// baseline (speedup 1.0000x reference)
#include <cuda_runtime.h>
#include <cuda_bf16.h>
#include <cuda_fp16.h>
#include <cstdint>

// Problem constants (fixed by the dataset)
#define NN   50000
#define EE   800000
#define FIN  128
#define HH   4
#define DHH  64
#define HID  256   // HH*DHH

// ---------------- static device scratch ----------------
__device__ __half   g_feat16[(size_t)NN * HID];      // feat stored fp16 (gather-only consumer)
__device__ float    g_res [(size_t)NN * HID];
__device__ float    g_h1  [(size_t)NN * HID];
__device__ float    g_h2  [(size_t)NN * HID];
__device__ float    g_el  [(size_t)NN * HH];
__device__ float    g_er  [(size_t)NN * HH];
__device__ unsigned g_gmax[8];                        // per-head global max: el[0..3], er[4..7]
__device__ unsigned g_Bh  [(size_t)HID / 2 * HID];   // packed bf16 pairs along K
__device__ unsigned g_Bl  [(size_t)HID / 2 * HID];
__device__ int      g_deg   [NN];
__device__ int      g_rowptr[NN + 1];
__device__ int      g_cursor[NN];
__device__ int      g_esrc  [EE];

__device__ __forceinline__ unsigned enc_f(float v) {
    unsigned b = __float_as_uint(v);
    return (b & 0x80000000u) ? ~b : (b | 0x80000000u);
}
__device__ __forceinline__ float dec_f(unsigned u) {
    unsigned b = (u & 0x80000000u) ? (u ^ 0x80000000u) : ~u;
    return __uint_as_float(b);
}
__device__ __forceinline__ unsigned pack_bf16(float a, float b) {
    unsigned r;
    asm("cvt.rn.bf16x2.f32 %0, %1, %2;" : "=r"(r) : "f"(b), "f"(a));
    return r;
}
__device__ __forceinline__ float bf16_hi_f(float w) {
    return __bfloat162float(__float2bfloat16(w));
}

// ============ B pre-conversion: W[K,N] fp32 -> packed bf16 hi/lo pairs along K ============
__global__ void convW_k(const float* __restrict__ W, unsigned* __restrict__ Bh,
                        unsigned* __restrict__ Bl, int K2, int N)
{
    int i = blockIdx.x * blockDim.x + threadIdx.x;
    if (i >= K2 * N) return;
    int k2 = i / N, n = i - k2 * N;
    float w0 = W[(size_t)(2 * k2) * N + n];
    float w1 = W[(size_t)(2 * k2 + 1) * N + n];
    float h0 = bf16_hi_f(w0), h1 = bf16_hi_f(w1);
    Bh[i] = pack_bf16(h0, h1);
    Bl[i] = pack_bf16(w0 - h0, w1 - h1);
}

// ================= GEMM: C = A @ B via 3xBF16 m16n8k16, double-buffered =================
#define MMA_BF16(d, a, b0, b1)                                               \
    asm volatile("mma.sync.aligned.m16n8k16.row.col.f32.bf16.bf16.f32 "      \
                 "{%0,%1,%2,%3}, {%4,%5,%6,%7}, {%8,%9}, {%0,%1,%2,%3};"     \
                 : "+f"(d[0]), "+f"(d[1]), "+f"(d[2]), "+f"(d[3])            \
                 : "r"(a[0]), "r"(a[1]), "r"(a[2]), "r"(a[3]),               \
                   "r"(b0), "r"(b1))

#define BM 128
#define BN 64
#define BK 16
#define APAD 12
#define BPAD 72

// FUSE=true: write feat as fp16 + fused el/er.  FUSE=false: write fp32 C.
template<bool FUSE>
__global__ void __launch_bounds__(128) gemm_bf16x3(
    const float* __restrict__ A,
    const unsigned* __restrict__ Bhg, const unsigned* __restrict__ Blg,
    float* __restrict__ C, __half* __restrict__ F16,
    const float* __restrict__ al, const float* __restrict__ ar,
    float* __restrict__ el, float* __restrict__ er,
    int M, int K, int N)
{
    __shared__ unsigned Ah[2][BM * APAD], Al[2][BM * APAD];
    __shared__ unsigned Bh[2][8 * BPAD], Bl[2][8 * BPAD];

    const int tid  = threadIdx.x;
    const int lane = tid & 31;
    const int wid  = tid >> 5;
    const int rowBase = blockIdx.y * BM;
    const int colBase = blockIdx.x * BN;

    float c[2][8][4];
#pragma unroll
    for (int mt = 0; mt < 2; mt++)
#pragma unroll
        for (int nt = 0; nt < 8; nt++)
#pragma unroll
            for (int i = 0; i < 4; i++) c[mt][nt][i] = 0.f;

    float4 av[4];
    uint4  bhv, blv;

    const int aRow  = tid >> 2;
    const int aCol4 = (tid & 3) << 2;
    const int bR    = tid >> 4;
    const int bC4   = (tid & 15) << 2;

    auto ldgA = [&](int kt) {
#pragma unroll
        for (int i = 0; i < 4; i++) {
            int gr = rowBase + aRow + 32 * i;
            av[i] = (gr < M) ? *(const float4*)(A + (size_t)gr * K + kt + aCol4)
                             : make_float4(0.f, 0.f, 0.f, 0.f);
        }
    };
    auto ldgB = [&](int kt) {
        size_t off = (size_t)(kt / 2 + bR) * N + colBase + bC4;
        bhv = *(const uint4*)(Bhg + off);
        blv = *(const uint4*)(Blg + off);
    };
    auto stsAB = [&](int buf) {
#pragma unroll
        for (int i = 0; i < 4; i++) {
            float hx = bf16_hi_f(av[i].x), hy = bf16_hi_f(av[i].y);
            float hz = bf16_hi_f(av[i].z), hw = bf16_hi_f(av[i].w);
            int idx = (aRow + 32 * i) * APAD + (aCol4 >> 1);
            *(uint2*)&Ah[buf][idx] = make_uint2(pack_bf16(hx, hy), pack_bf16(hz, hw));
            *(uint2*)&Al[buf][idx] = make_uint2(pack_bf16(av[i].x - hx, av[i].y - hy),
                                                pack_bf16(av[i].z - hz, av[i].w - hw));
        }
        int bidx = bR * BPAD + bC4;
        *(uint4*)&Bh[buf][bidx] = bhv;
        *(uint4*)&Bl[buf][bidx] = blv;
    };

    ldgA(0); ldgB(0);
    stsAB(0);
    __syncthreads();

    const int ntiles = K / BK;
    for (int t = 0; t < ntiles; t++) {
        const int buf = t & 1;
        if (t + 1 < ntiles) { ldgA((t + 1) * BK); ldgB((t + 1) * BK); }

        unsigned ah[2][4], alr[2][4];
#pragma unroll
        for (int mt = 0; mt < 2; mt++) {
            int r  = wid * 32 + mt * 16 + (lane >> 2);
            int c0 = lane & 3;
            ah [mt][0] = Ah[buf][r * APAD + c0];
            ah [mt][1] = Ah[buf][(r + 8) * APAD + c0];
            ah [mt][2] = Ah[buf][r * APAD + c0 + 4];
            ah [mt][3] = Ah[buf][(r + 8) * APAD + c0 + 4];
            alr[mt][0] = Al[buf][r * APAD + c0];
            alr[mt][1] = Al[buf][(r + 8) * APAD + c0];
            alr[mt][2] = Al[buf][r * APAD + c0 + 4];
            alr[mt][3] = Al[buf][(r + 8) * APAD + c0 + 4];
        }
#pragma unroll
        for (int nt = 0; nt < 8; nt++) {
            int col = nt * 8 + (lane >> 2);
            int kr  = lane & 3;
            unsigned bh0 = Bh[buf][kr * BPAD + col], bh1 = Bh[buf][(kr + 4) * BPAD + col];
            unsigned bl0 = Bl[buf][kr * BPAD + col], bl1 = Bl[buf][(kr + 4) * BPAD + col];
#pragma unroll
            for (int mt = 0; mt < 2; mt++) {
                MMA_BF16(c[mt][nt], ah[mt],  bh0, bh1);
                MMA_BF16(c[mt][nt], alr[mt], bh0, bh1);
                MMA_BF16(c[mt][nt], ah[mt],  bl0, bl1);
            }
        }
        if (t + 1 < ntiles) stsAB(buf ^ 1);
        __syncthreads();
    }

    // ---- store: fp16 feat (FUSE) or fp32 C (residual) ----
#pragma unroll
    for (int mt = 0; mt < 2; mt++) {
        int r0 = rowBase + wid * 32 + mt * 16 + (lane >> 2);
        int r1 = r0 + 8;
#pragma unroll
        for (int nt = 0; nt < 8; nt++) {
            int cc = colBase + nt * 8 + (lane & 3) * 2;
            if (FUSE) {
                if (r0 < M) *(__half2*)(F16 + (size_t)r0 * N + cc) =
                    __floats2half2_rn(c[mt][nt][0], c[mt][nt][1]);
                if (r1 < M) *(__half2*)(F16 + (size_t)r1 * N + cc) =
                    __floats2half2_rn(c[mt][nt][2], c[mt][nt][3]);
            } else {
                if (r0 < M) *(float2*)(C + (size_t)r0 * N + cc) = make_float2(c[mt][nt][0], c[mt][nt][1]);
                if (r1 < M) *(float2*)(C + (size_t)r1 * N + cc) = make_float2(c[mt][nt][2], c[mt][nt][3]);
            }
        }
    }

    // ---- fused el/er: this col-block is exactly head h = blockIdx.x ----
    if (FUSE) {
        int h = blockIdx.x;
        float alv[16], arv[16];
#pragma unroll
        for (int nt = 0; nt < 8; nt++)
#pragma unroll
            for (int j = 0; j < 2; j++) {
                int cc = nt * 8 + (lane & 3) * 2 + j;
                alv[nt * 2 + j] = al[h * 64 + cc];
                arv[nt * 2 + j] = ar[h * 64 + cc];
            }
#pragma unroll
        for (int mt = 0; mt < 2; mt++) {
            float e0 = 0, e1 = 0, f0 = 0, f1 = 0;
#pragma unroll
            for (int nt = 0; nt < 8; nt++)
#pragma unroll
                for (int j = 0; j < 2; j++) {
                    e0 += c[mt][nt][j]     * alv[nt * 2 + j];
                    e1 += c[mt][nt][2 + j] * alv[nt * 2 + j];
                    f0 += c[mt][nt][j]     * arv[nt * 2 + j];
                    f1 += c[mt][nt][2 + j] * arv[nt * 2 + j];
                }
#pragma unroll
            for (int off = 1; off < 4; off <<= 1) {
                e0 += __shfl_xor_sync(0xffffffffu, e0, off);
                e1 += __shfl_xor_sync(0xffffffffu, e1, off);
                f0 += __shfl_xor_sync(0xffffffffu, f0, off);
                f1 += __shfl_xor_sync(0xffffffffu, f1, off);
            }
            if ((lane & 3) == 0) {
                int r0 = rowBase + wid * 32 + mt * 16 + (lane >> 2);
                int r1 = r0 + 8;
                if (r0 < M) { el[(size_t)r0 * HH + h] = e0; er[(size_t)r0 * HH + h] = f0; }
                if (r1 < M) { el[(size_t)r1 * HH + h] = e1; er[(size_t)r1 * HH + h] = f1; }
            }
        }
    }
}

// ================= per-head global max of el and er =================
__global__ void headmax_k(const float* __restrict__ el, const float* __restrict__ er,
                          unsigned* __restrict__ gmax, int NH)
{
    int t = blockIdx.x * blockDim.x + threadIdx.x;
    int stride = gridDim.x * blockDim.x;
    float mel = -1e30f, mer = -1e30f;
    for (int i = t; i < NH; i += stride) {
        mel = fmaxf(mel, el[i]);
        mer = fmaxf(mer, er[i]);
    }
#pragma unroll
    for (int off = 4; off < 32; off <<= 1) {
        mel = fmaxf(mel, __shfl_xor_sync(0xffffffffu, mel, off));
        mer = fmaxf(mer, __shfl_xor_sync(0xffffffffu, mer, off));
    }
    int lane = threadIdx.x & 31;
    if (lane < 4) {
        atomicMax(&gmax[lane],     enc_f(mel));
        atomicMax(&gmax[4 + lane], enc_f(mer));
    }
}

// ================= CSR build (once; edges shared by all layers) =================
__global__ void hist_k(const int* __restrict__ dst, int* deg, int E)
{
    int i = blockIdx.x * blockDim.x + threadIdx.x;
    if (i < E) atomicAdd(&deg[dst[i]], 1);
}

__global__ void scan_k(const int* __restrict__ deg, int* __restrict__ rowptr,
                       int* __restrict__ cursor, int n, int E)
{
    const int C = (n + 1023) >> 10;
    int t = threadIdx.x;
    int base = t * C;
    int s = 0;
    for (int i = 0; i < C; i++) { int id = base + i; if (id < n) s += deg[id]; }
    __shared__ int sm[1024];
    sm[t] = s;
    __syncthreads();
    for (int off = 1; off < 1024; off <<= 1) {
        int v = (t >= off) ? sm[t - off] : 0;
        __syncthreads();
        sm[t] += v;
        __syncthreads();
    }
    int run = sm[t] - s;
    for (int i = 0; i < C; i++) {
        int id = base + i;
        if (id < n) { rowptr[id] = run; cursor[id] = run; run += deg[id]; }
    }
    if (t == 0) rowptr[n] = E;
}

__global__ void scatter_k(const int* __restrict__ src, const int* __restrict__ dst,
                          int* cursor, int* __restrict__ esrc, int E)
{
    int i = blockIdx.x * blockDim.x + threadIdx.x;
    if (i >= E) return;
    int p = atomicAdd(&cursor[dst[i]], 1);
    esrc[p] = src[i];
}

// ======== GAT aggregation: 2 warps/node, EDGE-split; lane owns 8 cols (1 uint4) ========
template<int MODE>
__global__ void __launch_bounds__(256) gat_node_k(
    const uint4* __restrict__ feat4,          // fp16 rows: 32 uint4 per row
    const int* __restrict__ rowptr, const int* __restrict__ esrc,
    const float* __restrict__ el, const float* __restrict__ er,
    const unsigned* __restrict__ gmax,
    const float4* __restrict__ res4, const float4* __restrict__ bias4,
    float* __restrict__ out)
{
    __shared__ float sacc[4][32][8];
    __shared__ float sden[4][32];

    int w    = threadIdx.x >> 5;
    int lane = threadIdx.x & 31;
    int gw   = blockIdx.x * 8 + w;
    int node = gw >> 1;
    int half = gw & 1;
    int nib  = w >> 1;                 // node index within block (0..3)
    bool active = node < NN;

    int h = lane >> 3;                 // head for this lane's 8 columns
    float acc[8];
#pragma unroll
    for (int j = 0; j < 8; j++) acc[j] = 0.f;
    float den = 0.f;

    if (active) {
        int start = rowptr[node], end = rowptr[node + 1];
        int cnt = end - start;
        int mid = start + (cnt >> 1);
        int ib  = half ? mid : start;
        int ie  = half ? end : mid;

        float m   = dec_f(gmax[h]) + dec_f(gmax[4 + h]);
        float erB = er[(size_t)node * HH + h];

        int idx = ib;
        for (; idx + 4 <= ie; idx += 4) {
            int s0 = esrc[idx], s1 = esrc[idx + 1], s2 = esrc[idx + 2], s3 = esrc[idx + 3];
            float e0 = el[(size_t)s0 * HH + h];
            float e1 = el[(size_t)s1 * HH + h];
            float e2 = el[(size_t)s2 * HH + h];
            float e3 = el[(size_t)s3 * HH + h];
            uint4 u0 = feat4[(size_t)s0 * 32 + lane];
            uint4 u1 = feat4[(size_t)s1 * 32 + lane];
            uint4 u2 = feat4[(size_t)s2 * 32 + lane];
            uint4 u3 = feat4[(size_t)s3 * 32 + lane];
            float v0 = e0 + erB; v0 = v0 > 0.f ? v0 : 0.2f * v0;
            float v1 = e1 + erB; v1 = v1 > 0.f ? v1 : 0.2f * v1;
            float v2 = e2 + erB; v2 = v2 > 0.f ? v2 : 0.2f * v2;
            float v3 = e3 + erB; v3 = v3 > 0.f ? v3 : 0.2f * v3;
            float w0 = __expf(v0 - m), w1 = __expf(v1 - m);
            float w2 = __expf(v2 - m), w3 = __expf(v3 - m);
            den += (w0 + w1) + (w2 + w3);
#pragma unroll
            for (int q = 0; q < 4; q++) {
                unsigned uu0 = (&u0.x)[q], uu1 = (&u1.x)[q], uu2 = (&u2.x)[q], uu3 = (&u3.x)[q];
                float2 p0 = __half22float2(*(const __half2*)&uu0);
                float2 p1 = __half22float2(*(const __half2*)&uu1);
                float2 p2 = __half22float2(*(const __half2*)&uu2);
                float2 p3 = __half22float2(*(const __half2*)&uu3);
                acc[2 * q]     += w0 * p0.x + w1 * p1.x + w2 * p2.x + w3 * p3.x;
                acc[2 * q + 1] += w0 * p0.y + w1 * p1.y + w2 * p2.y + w3 * p3.y;
            }
        }
        for (; idx < ie; idx++) {
            int s0 = esrc[idx];
            float e0 = el[(size_t)s0 * HH + h];
            uint4 u0 = feat4[(size_t)s0 * 32 + lane];
            float v0 = e0 + erB; v0 = v0 > 0.f ? v0 : 0.2f * v0;
            float w0 = __expf(v0 - m);
            den += w0;
#pragma unroll
            for (int q = 0; q < 4; q++) {
                unsigned uu0 = (&u0.x)[q];
                float2 p0 = __half22float2(*(const __half2*)&uu0);
                acc[2 * q]     += w0 * p0.x;
                acc[2 * q + 1] += w0 * p0.y;
            }
        }
    }

    // ---- cross-warp combine: warp `half==1` publishes, warp `half==0` finalizes ----
    if (half == 1) {
#pragma unroll
        for (int j = 0; j < 8; j++) sacc[nib][lane][j] = acc[j];
        sden[nib][lane] = den;
    }
    __syncthreads();
    if (half == 0 && active) {
#pragma unroll
        for (int j = 0; j < 8; j++) acc[j] += sacc[nib][lane][j];
        den += sden[nib][lane];
        float inv = 1.f / fmaxf(den, 1e-16f);

        float4 r0 = res4[(size_t)node * 64 + lane * 2];
        float4 r1 = res4[(size_t)node * 64 + lane * 2 + 1];
        float4 b0 = bias4[lane * 2];
        float4 b1 = bias4[lane * 2 + 1];

        float v0 = acc[0] * inv + r0.x + b0.x;
        float v1 = acc[1] * inv + r0.y + b0.y;
        float v2 = acc[2] * inv + r0.z + b0.z;
        float v3 = acc[3] * inv + r0.w + b0.w;
        float v4 = acc[4] * inv + r1.x + b1.x;
        float v5 = acc[5] * inv + r1.y + b1.y;
        float v6 = acc[6] * inv + r1.z + b1.z;
        float v7 = acc[7] * inv + r1.w + b1.w;

        if (MODE == 0) {
            float4* o4 = (float4*)out + (size_t)node * 64 + lane * 2;
            o4[0] = make_float4(fmaxf(v0, 0.f), fmaxf(v1, 0.f), fmaxf(v2, 0.f), fmaxf(v3, 0.f));
            o4[1] = make_float4(fmaxf(v4, 0.f), fmaxf(v5, 0.f), fmaxf(v6, 0.f), fmaxf(v7, 0.f));
        } else {
            // mean over heads: lanes l, l^8, l^16, l^24 hold the same within-head column set
#pragma unroll
            for (int off = 8; off < 32; off <<= 1) {
                v0 += __shfl_xor_sync(0xffffffffu, v0, off);
                v1 += __shfl_xor_sync(0xffffffffu, v1, off);
                v2 += __shfl_xor_sync(0xffffffffu, v2, off);
                v3 += __shfl_xor_sync(0xffffffffu, v3, off);
                v4 += __shfl_xor_sync(0xffffffffu, v4, off);
                v5 += __shfl_xor_sync(0xffffffffu, v5, off);
                v6 += __shfl_xor_sync(0xffffffffu, v6, off);
                v7 += __shfl_xor_sync(0xffffffffu, v7, off);
            }
            if (lane < 8) {
                float4* oy = (float4*)out + (size_t)node * 16 + lane * 2;
                oy[0] = make_float4(v0 * 0.25f, v1 * 0.25f, v2 * 0.25f, v3 * 0.25f);
                oy[1] = make_float4(v4 * 0.25f, v5 * 0.25f, v6 * 0.25f, v7 * 0.25f);
            }
        }
    }
}

// ================= host orchestration =================
extern "C" void kernel_launch(void* const* d_in, const int* in_sizes, int n_in,
                              void* d_out, int out_size)
{
    const float* x  = (const float*)d_in[0];
    const int*   ei = (const int*)d_in[1];
    const int E  = in_sizes[1] / 2;
    const int Nn = in_sizes[0] / FIN;
    const int* src = ei;
    const int* dst = ei + E;
    const float* W[3]  = {(const float*)d_in[2],  (const float*)d_in[3],  (const float*)d_in[4]};
    const float* al[3] = {(const float*)d_in[5],  (const float*)d_in[6],  (const float*)d_in[7]};
    const float* ar[3] = {(const float*)d_in[8],  (const float*)d_in[9],  (const float*)d_in[10]};
    const float* bb[3] = {(const float*)d_in[11], (const float*)d_in[12], (const float*)d_in[13]};
    const float* resW0 = (const float*)d_in[14];

    __half* feat16;
    float *res, *h1, *h2, *el, *er;
    unsigned *gmax, *Bh, *Bl;
    int *deg, *rowptr, *cursor, *esrc;
    cudaGetSymbolAddress((void**)&feat16, g_feat16);
    cudaGetSymbolAddress((void**)&res,    g_res);
    cudaGetSymbolAddress((void**)&h1,     g_h1);
    cudaGetSymbolAddress((void**)&h2,     g_h2);
    cudaGetSymbolAddress((void**)&el,     g_el);
    cudaGetSymbolAddress((void**)&er,     g_er);
    cudaGetSymbolAddress((void**)&gmax,   g_gmax);
    cudaGetSymbolAddress((void**)&Bh,     g_Bh);
    cudaGetSymbolAddress((void**)&Bl,     g_Bl);
    cudaGetSymbolAddress((void**)&deg,    g_deg);
    cudaGetSymbolAddress((void**)&rowptr, g_rowptr);
    cudaGetSymbolAddress((void**)&cursor, g_cursor);
    cudaGetSymbolAddress((void**)&esrc,   g_esrc);

    const dim3 gemmGrid(HID / BN, (Nn + BM - 1) / BM);
    const int nodeGrid = (2 * Nn + 7) / 8;
    const int NH = Nn * HH;

    // ---- CSR by dst (edges identical for all 3 layers) ----
    cudaMemsetAsync(deg, 0, (size_t)Nn * sizeof(int), 0);
    hist_k<<<(E + 255) / 256, 256>>>(dst, deg, E);
    scan_k<<<1, 1024>>>(deg, rowptr, cursor, Nn, E);
    scatter_k<<<(E + 255) / 256, 256>>>(src, dst, cursor, esrc, E);

    auto layer = [&](const float* A, int K, const float* Wc, const float* alc, const float* arc) {
        convW_k<<<(K / 2 * HID + 255) / 256, 256>>>(Wc, Bh, Bl, K / 2, HID);
        gemm_bf16x3<true><<<gemmGrid, 128>>>(A, Bh, Bl, nullptr, feat16, alc, arc, el, er, Nn, K, HID);
        cudaMemsetAsync(gmax, 0, 8 * sizeof(unsigned), 0);
        headmax_k<<<64, 256>>>(el, er, gmax, NH);
    };

    // ---- Layer 0 ----
    layer(x, FIN, W[0], al[0], ar[0]);
    convW_k<<<(FIN / 2 * HID + 255) / 256, 256>>>(resW0, Bh, Bl, FIN / 2, HID);
    gemm_bf16x3<false><<<gemmGrid, 128>>>(x, Bh, Bl, res, nullptr, nullptr, nullptr, nullptr, nullptr, Nn, FIN, HID);
    gat_node_k<0><<<nodeGrid, 256>>>((const uint4*)feat16, rowptr, esrc, el, er, gmax,
                                     (const float4*)res, (const float4*)bb[0], h1);

    // ---- Layer 1 ----
    layer(h1, HID, W[1], al[1], ar[1]);
    gat_node_k<0><<<nodeGrid, 256>>>((const uint4*)feat16, rowptr, esrc, el, er, gmax,
                                     (const float4*)h1, (const float4*)bb[1], h2);

    // ---- Layer 2 ----
    layer(h2, HID, W[2], al[2], ar[2]);
    gat_node_k<2><<<nodeGrid, 256>>>((const uint4*)feat16, rowptr, esrc, el, er, gmax,
                                     (const float4*)h2, (const float4*)bb[2], (float*)d_out);
}